// round 9
// baseline (speedup 1.0000x reference)
#include <cuda_runtime.h>
#include <cuda_bf16.h>

// ---------------------------------------------------------------------------
// LocalAttention: x[8,128,128,128] --1x1 convs(W1,W2,W3:[64,128])--> q,k,v
// --9x9 dilated(2) local attention--> out[8,64,128,128], all fp32.
//
// Parity trick: dilation-2 only mixes same-parity pixels; 4 interleaved 64x64
// subgrids with dense 9x9 neighborhoods. K/V live in zero-padded 72x72 planes
// (borders stay zero: __device__ globals are zero-initialized; only interiors
// are written), so the attention kernel needs no bounds checks.
//
// v5 attention ("global-operand"): K and V are read straight from global
// memory with broadcast-coalesced LDG (L1-served; per-c K slice is 1KB and
// warps advance through c together, V rows are shared across the 9 query
// rows). No K/V smem staging, no cross-warp barriers between S, softmax and
// O: P rows are warp-local in smem, 1/sum stays in registers. smem = Q tile
// + P only = 53KB -> 3 CTAs/SM (24 warps).
// (Round-8 fix: restore cudaFuncSetAttribute — 53KB > 48KB default dynamic
// smem; its absence made every capture launch fail.)
// ---------------------------------------------------------------------------

#define NIMG 8
#define CIN  128
#define COUT 64
#define HW   128
#define NSUB 32              // 8 images * 4 parities
#define PADD 72              // 64 + 2*4 halo
#define PPLANE (PADD*PADD)   // 5184

// scratch (device-global; zero-initialized at module load)
__device__ __align__(16) float g_Q[(size_t)NSUB * 64 * 4096];   // [sub][c][sy*64+sx]
__device__ __align__(16) float g_K[(size_t)NSUB * 64 * PPLANE]; // [sub][c][(sy+4)*72+(sx+4)]
__device__ __align__(16) float g_V[(size_t)NSUB * PPLANE * 64]; // [sub][(sy+4)*72+(sx+4)][c]
__device__ __align__(16) float g_Wt[128 * 192];                 // [c][o] o:0-63 W1|64-127 W2|128-191 W3

// ---- packed f32x2 helpers --------------------------------------------------
typedef unsigned long long u64;

__device__ __forceinline__ u64 pk2(float a, float b) {
    u64 r; asm("mov.b64 %0, {%1, %2};" : "=l"(r) : "f"(a), "f"(b)); return r;
}
__device__ __forceinline__ void up2(u64 v, float& a, float& b) {
    asm("mov.b64 {%0, %1}, %2;" : "=f"(a), "=f"(b) : "l"(v));
}
__device__ __forceinline__ void fma2(u64& d, u64 a, u64 b) {
    asm("fma.rn.f32x2 %0, %1, %2, %3;" : "=l"(d) : "l"(a), "l"(b), "l"(d));
}
// shared: two packed f32x2 (16B)
__device__ __forceinline__ void lds2(u64& a, u64& b, const float* p) {
    unsigned sp = (unsigned)__cvta_generic_to_shared(p);
    asm volatile("ld.shared.v2.b64 {%0, %1}, [%2];" : "=l"(a), "=l"(b) : "r"(sp));
}
// global read-only: two packed f32x2 (16B)
__device__ __forceinline__ void ldg2(u64& a, u64& b, const float* p) {
    asm volatile("ld.global.nc.v2.u64 {%0, %1}, [%2];" : "=l"(a), "=l"(b) : "l"(p));
}
// global read-only: one packed f32x2 (8B)
__device__ __forceinline__ u64 ldg1(const float* p) {
    u64 a; asm volatile("ld.global.nc.u64 %0, [%1];" : "=l"(a) : "l"(p));
    return a;
}

// ---------------------------------------------------------------------------
// Kernel 0: transpose weights -> g_Wt[c][o]  (tiny)
// ---------------------------------------------------------------------------
__global__ void wt_kernel(const float* __restrict__ W1,
                          const float* __restrict__ W2,
                          const float* __restrict__ W3)
{
    int i = blockIdx.x * 256 + threadIdx.x;     // 24576 total
    if (i >= 192 * 128) return;
    int o = i >> 7, c = i & 127;
    const float* Wt = (o < 64) ? W1 : ((o < 128) ? W2 : W3);
    g_Wt[c * 192 + o] = Wt[(o & 63) * 128 + c];
}

// ---------------------------------------------------------------------------
// Kernel 1: fused 1x1 convs.  CTA = (wh, h, n): 64-px half row x 192 oc.
// smem: xs[128c][64w] = 32KB only; W read via warp-uniform LDG (L1-resident).
// Thread (w_t=tid%16 -> 4w, oc_t=tid/16 -> 12oc). 3 CTAs/SM.
// ---------------------------------------------------------------------------
#define CONV_SMEM_FLOATS 8192
__global__ __launch_bounds__(256, 3) void conv_kernel(
    const float* __restrict__ x)
{
    extern __shared__ float sm[];
    float* xs = sm;                 // [128][64]

    const int tid = threadIdx.x;
    const int wh  = blockIdx.x;     // 0/1 half of the row
    const int h   = blockIdx.y;
    const int n   = blockIdx.z;
    const int w0  = wh * 64;
    const int w_t = tid & 15;
    const int oc_t = tid >> 4;

    const float* xbase = x + ((size_t)n * CIN) * HW * HW + (size_t)h * HW + w0;
    #pragma unroll
    for (int it = 0; it < 8; it++) {
        int i = it * 256 + tid;                 // 2048 float4
        int c = i >> 4, w4 = (i & 15) << 2;
        *(float4*)&xs[c * 64 + w4] =
            *(const float4*)(xbase + (size_t)c * HW * HW + w4);
    }
    __syncthreads();

    u64 acc[12][2];
    #pragma unroll
    for (int j = 0; j < 12; j++) { acc[j][0] = 0ull; acc[j][1] = 0ull; }

    const float* wrow = g_Wt + 12 * oc_t;
    #pragma unroll 4
    for (int c = 0; c < 128; c++) {
        u64 xp0, xp1;
        lds2(xp0, xp1, &xs[c * 64 + 4 * w_t]);
        const float4 wa = __ldg((const float4*)(wrow + c * 192));
        const float4 wb = __ldg((const float4*)(wrow + c * 192 + 4));
        const float4 wc = __ldg((const float4*)(wrow + c * 192 + 8));
        float wv[12] = {wa.x, wa.y, wa.z, wa.w, wb.x, wb.y, wb.z, wb.w,
                        wc.x, wc.y, wc.z, wc.w};
        #pragma unroll
        for (int j = 0; j < 12; j++) {
            u64 s = pk2(wv[j], wv[j]);
            fma2(acc[j][0], s, xp0);
            fma2(acc[j][1], s, xp1);
        }
    }

    float ov[12][4];
    #pragma unroll
    for (int j = 0; j < 12; j++) {
        up2(acc[j][0], ov[j][0], ov[j][1]);
        up2(acc[j][1], ov[j][2], ov[j][3]);
    }
    const int sy  = h >> 1;
    const int ph2 = (h & 1) * 2;
    const int sub_e = n * 4 + ph2;
    const int sub_o = sub_e + 1;
    const int sx0 = wh * 32 + 2 * w_t;

    #pragma unroll
    for (int j = 0; j < 12; j++) {
        int o = 12 * oc_t + j;
        if (o < 64) {            // Q
            size_t be = ((size_t)(sub_e * 64 + o)) * 4096 + sy * 64 + sx0;
            size_t bo = ((size_t)(sub_o * 64 + o)) * 4096 + sy * 64 + sx0;
            *(float2*)(g_Q + be) = make_float2(ov[j][0], ov[j][2]);
            *(float2*)(g_Q + bo) = make_float2(ov[j][1], ov[j][3]);
        } else if (o < 128) {    // K
            int oc = o - 64;
            size_t be = ((size_t)(sub_e * 64 + oc)) * PPLANE + (sy + 4) * PADD + 4 + sx0;
            size_t bo = ((size_t)(sub_o * 64 + oc)) * PPLANE + (sy + 4) * PADD + 4 + sx0;
            *(float2*)(g_K + be) = make_float2(ov[j][0], ov[j][2]);
            *(float2*)(g_K + bo) = make_float2(ov[j][1], ov[j][3]);
        }
    }

    __syncthreads();           // xs reads done; reuse as vsm[64 w][68]
    float* vsm = sm;
    #pragma unroll
    for (int j = 0; j < 12; j++) {
        int o = 12 * oc_t + j;
        if (o >= 128) {
            int oc = o - 128;
            #pragma unroll
            for (int jj = 0; jj < 4; jj++)
                vsm[(4 * w_t + jj) * 68 + oc] = ov[j][jj];
        }
    }
    __syncthreads();
    #pragma unroll
    for (int it = 0; it < 4; it++) {
        int i = it * 256 + tid;                 // 1024 float4: (wl 64, c4 16)
        int c4 = i & 15, wl = i >> 4;
        float4 v = *(float4*)&vsm[wl * 68 + c4 * 4];
        int w = w0 + wl;
        int pw = w & 1, sx = w >> 1;
        int sub = n * 4 + ph2 + pw;
        size_t a = ((size_t)sub * PPLANE + (sy + 4) * PADD + sx + 4) * 64 + c4 * 4;
        *(float4*)(g_V + a) = v;
    }
}

// ---------------------------------------------------------------------------
// Kernel 2: local attention per 8x8 pixel tile; 256 threads, 3 CTAs/SM.
// smem (floats): Qs [64c][64px] @ 0 (4096), P [64px][148] @ 4096 (9472).
// K and V are read directly from global (L1). No barriers between S,
// softmax and O phases: P rows and 1/sum are warp-local.
// ---------------------------------------------------------------------------
#define OFF_Q 0
#define OFF_P 4096
#define PP    148
#define OFF_O 4096                 // O staging overlays P after final barrier
#define ATTN_SMEM_FLOATS 13568     // 53KB -> 3 CTAs/SM

__global__ __launch_bounds__(256, 3) void attn_kernel(float* __restrict__ out)
{
    extern __shared__ float sm[];
    const int tid  = threadIdx.x;
    const int lane = tid & 31;
    const int tile = blockIdx.x;          // 0..63
    const int sub  = blockIdx.y;          // 0..31
    const int by = tile >> 3, bx = tile & 7;

    // ---- load Q tile cooperatively ----------------------------------------
    #pragma unroll
    for (int it = 0; it < 4; it++) {
        int i = it * 256 + tid;           // 1024 float4: (c 64, ty 8, f4 2)
        int f4 = i & 1, ty = (i >> 1) & 7, c = i >> 4;
        const float* src = g_Q + ((size_t)(sub * 64 + c)) * 4096
                         + (by * 8 + ty) * 64 + bx * 8 + f4 * 4;
        *(float4*)&sm[OFF_Q + c * 64 + ty * 8 + f4 * 4] = *(const float4*)src;
    }
    __syncthreads();

    // ---- S = Q.K^T over the 9 valid halo rows, K from global ---------------
    const int ty    = tid >> 5;
    const int pos_t = lane;
    const int tx4   = lane * 4;

    const float* kbase = g_K + ((size_t)(sub * 64)) * PPLANE
                       + (by * 8 + ty) * PADD + bx * 8;
    const float* kmain = kbase + (pos_t >> 2) * PADD + (pos_t & 3) * 4;
    const float* kxp   = kbase + 8 * PADD + 2 * (lane & 7);

    u64 acc[8][2], accx[8];
    #pragma unroll
    for (int p = 0; p < 8; p++) { acc[p][0] = 0ull; acc[p][1] = 0ull; accx[p] = 0ull; }

    #pragma unroll 4
    for (int c = 0; c < 64; c++) {
        float4 qa = *(const float4*)&sm[OFF_Q + c * 64 + ty * 8];
        float4 qb = *(const float4*)&sm[OFF_Q + c * 64 + ty * 8 + 4];
        u64 kp0, kp1;
        ldg2(kp0, kp1, kmain + (size_t)c * PPLANE);
        u64 kx = ldg1(kxp + (size_t)c * PPLANE);
        float qv[8] = {qa.x, qa.y, qa.z, qa.w, qb.x, qb.y, qb.z, qb.w};
        #pragma unroll
        for (int p = 0; p < 8; p++) {
            u64 qs = pk2(qv[p], qv[p]);
            fma2(acc[p][0], qs, kp0);
            fma2(acc[p][1], qs, kp1);
            fma2(accx[p],  qs, kx);
        }
    }

    // ---- streamed per-row mask + lazy softmax + P store (warp-local) -------
    float inv[8];
    #pragma unroll
    for (int p = 0; p < 8; p++) {
        float s0, s1, s2, s3, e0, e1;
        up2(acc[p][0], s0, s1);
        up2(acc[p][1], s2, s3);
        up2(accx[p],   e0, e1);
        {
            int h0 = tx4 & 15, h1 = (tx4 + 1) & 15, h2 = (tx4 + 2) & 15, h3 = (tx4 + 3) & 15;
            if ((unsigned)(h0 - p) > 8u) s0 = -1e30f;
            if ((unsigned)(h1 - p) > 8u) s1 = -1e30f;
            if ((unsigned)(h2 - p) > 8u) s2 = -1e30f;
            if ((unsigned)(h3 - p) > 8u) s3 = -1e30f;
            int hx0 = 2 * (lane & 7), hx1 = hx0 + 1;
            if ((unsigned)(hx0 - p) > 8u) e0 = -1e30f;
            if ((unsigned)(hx1 - p) > 8u) e1 = -1e30f;
        }
        float m = fmaxf(fmaxf(s0, s1), fmaxf(s2, s3));
        if (lane < 8) m = fmaxf(m, fmaxf(e0, e1));
        #pragma unroll
        for (int k = 16; k >= 1; k >>= 1)
            m = fmaxf(m, __shfl_xor_sync(0xffffffffu, m, k));
        s0 = __expf(s0 - m); s1 = __expf(s1 - m);
        s2 = __expf(s2 - m); s3 = __expf(s3 - m);
        e0 = __expf(e0 - m); e1 = __expf(e1 - m);
        float sum = s0 + s1 + s2 + s3;
        if (lane < 8) sum += e0 + e1;
        #pragma unroll
        for (int k = 16; k >= 1; k >>= 1)
            sum += __shfl_xor_sync(0xffffffffu, sum, k);
        inv[p] = __fdividef(1.f, sum);

        const int px = ty * 8 + p;
        *(float4*)&sm[OFF_P + px * PP + tx4] = make_float4(s0, s1, s2, s3);
        if (lane < 8)
            *(float2*)&sm[OFF_P + px * PP + 128 + 2 * lane] = make_float2(e0, e1);
    }
    __syncwarp();     // P rows of this warp visible to all its lanes

    // ---- O = P.V over 144 positions, V from global -------------------------
    const int c_t = tid & 7;
    const int pxo = tid >> 3;
    const int px0 = 2 * pxo;
    const int oty = px0 >> 3;             // == own warp's ty
    u64 oacc[2][4];
    #pragma unroll
    for (int i = 0; i < 2; i++)
        #pragma unroll
        for (int j = 0; j < 4; j++) oacc[i][j] = 0ull;

    const float* Pr0 = &sm[OFF_P + px0 * PP];
    const float* Pr1 = &sm[OFF_P + (px0 + 1) * PP];
    const float* vbase = g_V + ((size_t)sub * PPLANE
                       + (by * 8 + oty) * PADD + bx * 8) * 64 + c_t * 8;

    #pragma unroll 3
    for (int r = 0; r < 9; r++) {
        const float* Vr = vbase + (size_t)r * (PADD * 64);
        const int pb = r * 16;
        #pragma unroll
        for (int hx = 0; hx < 16; hx++) {
            float p0 = Pr0[pb + hx];
            float p1 = Pr1[pb + hx];
            u64 pp0 = pk2(p0, p0), pp1 = pk2(p1, p1);
            u64 v0, v1, v2, v3;
            ldg2(v0, v1, Vr + hx * 64);
            ldg2(v2, v3, Vr + hx * 64 + 4);
            fma2(oacc[0][0], pp0, v0); fma2(oacc[0][1], pp0, v1);
            fma2(oacc[0][2], pp0, v2); fma2(oacc[0][3], pp0, v3);
            fma2(oacc[1][0], pp1, v0); fma2(oacc[1][1], pp1, v1);
            fma2(oacc[1][2], pp1, v2); fma2(oacc[1][3], pp1, v3);
        }
    }

    // select this thread's 1/sums from its own registers (p = 2*(pxo&3)(+1))
    const int sel = pxo & 3;
    float iv0 = (sel == 0) ? inv[0] : (sel == 1) ? inv[2] : (sel == 2) ? inv[4] : inv[6];
    float iv1 = (sel == 0) ? inv[1] : (sel == 1) ? inv[3] : (sel == 2) ? inv[5] : inv[7];

    __syncthreads();   // ALL P reads done; safe to overlay O staging onto P

    #pragma unroll
    for (int j = 0; j < 2; j++) {
        int px = px0 + j;
        float iv = j ? iv1 : iv0;
        float f[8];
        up2(oacc[j][0], f[0], f[1]); up2(oacc[j][1], f[2], f[3]);
        up2(oacc[j][2], f[4], f[5]); up2(oacc[j][3], f[6], f[7]);
        #pragma unroll
        for (int k = 0; k < 8; k++) f[k] *= iv;
        *(float4*)&sm[OFF_O + px * 68 + c_t * 8]     = make_float4(f[0], f[1], f[2], f[3]);
        *(float4*)&sm[OFF_O + px * 68 + c_t * 8 + 4] = make_float4(f[4], f[5], f[6], f[7]);
    }
    __syncthreads();

    // ---- store to out ------------------------------------------------------
    const int n  = sub >> 2;
    const int ph = (sub >> 1) & 1;
    const int pw = sub & 1;
    #pragma unroll
    for (int it = 0; it < 16; it++) {
        int i = it * 256 + tid;           // 4096: (ty 8, c 64, tx 8)
        int tx = i & 7, c = (i >> 3) & 63, tyy = i >> 9;
        float val = sm[OFF_O + (tyy * 8 + tx) * 68 + c];
        int hh = 2 * (by * 8 + tyy) + ph;
        int ww = 2 * (bx * 8 + tx) + pw;
        out[((size_t)(n * 64 + c)) * (HW * HW) + hh * HW + ww] = val;
    }
}

// ---------------------------------------------------------------------------
extern "C" void kernel_launch(void* const* d_in, const int* in_sizes, int n_in,
                              void* d_out, int out_size) {
    const float* x  = (const float*)d_in[0];
    const float* W1 = (const float*)d_in[1];
    const float* W2 = (const float*)d_in[2];
    const float* W3 = (const float*)d_in[3];
    float* out = (float*)d_out;
    (void)in_sizes; (void)n_in; (void)out_size;

    // 53KB dynamic smem > 48KB default: the opt-in attribute is REQUIRED
    // (its absence made every launch fail during round-8 capture).
    cudaFuncSetAttribute(attn_kernel, cudaFuncAttributeMaxDynamicSharedMemorySize,
                         ATTN_SMEM_FLOATS * 4);

    // 0) transpose weights into g_Wt[c][o]
    wt_kernel<<<96, 256>>>(W1, W2, W3);
    // 1) fused 1x1 convs (K/V borders stay zero from static zero-init)
    conv_kernel<<<dim3(2, HW, NIMG), 256, CONV_SMEM_FLOATS * 4>>>(x);
    // 2) local attention (K/V straight from global)
    attn_kernel<<<dim3(64, NSUB), 256, ATTN_SMEM_FLOATS * 4>>>(out);
}